// round 15
// baseline (speedup 1.0000x reference)
#include <cuda_runtime.h>
#include <cuda_fp16.h>
#include <math.h>

#define B 32
#define C 512
#define Q 128
#define D 768
#define NEG (-1e30f)
#define NCH 16
#define NCC 32

// ---------------- scratch ----------------------------------------------------
__device__ __half g_sim[(size_t)B * C * Q];      // fp16 sim (4.2 MB)
__device__ float g_Smax[B * C];
__device__ float g_pmax[B * NCH * Q];
__device__ float g_psum[B * NCH * Q];
__device__ float g_cdist[B * C];
__device__ float g_cdashp[NCC][B * D];
__device__ __align__(16) unsigned g_quesT[(size_t)B * D * (Q / 2)];

// ---------------- helpers ----------------------------------------------------
__device__ __forceinline__ unsigned pack_bf16(float lo, float hi) {
    unsigned r; asm("cvt.rn.bf16x2.f32 %0, %1, %2;" : "=r"(r) : "f"(hi), "f"(lo));
    return r;
}
__device__ __forceinline__ void mma_bf16(float* d, const unsigned* a, const unsigned* b) {
    asm volatile("mma.sync.aligned.m16n8k16.row.col.f32.bf16.bf16.f32 "
                 "{%0,%1,%2,%3}, {%4,%5,%6,%7}, {%8,%9}, {%0,%1,%2,%3};"
                 : "+f"(d[0]), "+f"(d[1]), "+f"(d[2]), "+f"(d[3])
                 : "r"(a[0]), "r"(a[1]), "r"(a[2]), "r"(a[3]), "r"(b[0]), "r"(b[1]));
}
__device__ __forceinline__ void ldsm4(unsigned* r, unsigned addr) {
    asm volatile("ldmatrix.sync.aligned.m8n8.x4.shared.b16 {%0,%1,%2,%3}, [%4];"
                 : "=r"(r[0]), "=r"(r[1]), "=r"(r[2]), "=r"(r[3]) : "r"(addr));
}
__device__ __forceinline__ void cp16(void* smem_dst, const void* gsrc) {
    unsigned ds = (unsigned)__cvta_generic_to_shared(smem_dst);
    asm volatile("cp.async.cg.shared.global [%0], [%1], 16;" :: "r"(ds), "l"(gsrc));
}
__device__ __forceinline__ void cp_commit() { asm volatile("cp.async.commit_group;"); }
__device__ __forceinline__ void cp_wait0()  { asm volatile("cp.async.wait_group 0;"); }

// ---------------- K1: sim GEMM (M-tile 64, 2 CTAs/SM) + fused ques transpose -
__global__ __launch_bounds__(256, 2) void k_sim_mma(const float* __restrict__ cont,
                                                    const float* __restrict__ ques,
                                                    const float* __restrict__ SW) {
    const int b  = blockIdx.z;
    const int cm = blockIdx.x * 64;
    extern __shared__ unsigned smemu[];
    unsigned* As = smemu;                      // [2][64][20]
    unsigned* Bs = smemu + 2 * 64 * 20;        // [2][128][20]
    float*   red = (float*)(Bs + 2 * 128 * 20); // 256
    float*  s_cw = red + 256;                  // 64
    float*  s_qw = s_cw + 64;                  // 128

    const int t = threadIdx.x, lane = t & 31, warp = t >> 5;
    const int g = lane >> 2, tg = lane & 3;
    const int wm2 = (warp & 1) * 32;
    const int wn2 = (warp >> 1) * 32;

    const int rA = (lane & 7) + (lane & 8);
    const int cA = (lane & 16) >> 2;
    const int rB = (lane & 7) + ((lane & 16) >> 1);
    const int cB = (lane & 8) >> 1;
    const unsigned aSh = (unsigned)__cvta_generic_to_shared(As);
    const unsigned bSh = (unsigned)__cvta_generic_to_shared(Bs);
    unsigned offA[2];
    offA[0] = ((wm2 + rA) * 20 + cA) * 4;
    offA[1] = offA[0] + 16 * 20 * 4;
    unsigned offB[2];
    #pragma unroll
    for (int p = 0; p < 2; p++) offB[p] = ((wn2 + p * 16 + rB) * 20 + cB) * 4;

    const float* w1 = SW;
    const float* w2 = SW + D;
    const float* w3 = SW + 2 * D;
    const int lrA = t >> 2, lkA = (t & 3) * 8, lwA = (t & 3) * 4;
    const int lrB = t >> 1, lkB = (t & 1) * 16, lwB = (t & 1) * 8;
    const float* Ag = cont + ((size_t)(b * C + cm + lrA)) * D + lkA;
    const float* Bg = ques + ((size_t)(b * Q + lrB)) * D + lkB;

    float acc[2][4][4];
    #pragma unroll
    for (int i = 0; i < 2; i++)
        #pragma unroll
        for (int j = 0; j < 4; j++)
            #pragma unroll
            for (int k = 0; k < 4; k++) acc[i][j][k] = 0.f;

    float cwacc = 0.f, qwacc = 0.f;

    float4 pa[2], pb[4];
    #pragma unroll
    for (int j = 0; j < 2; j++) pa[j] = *(const float4*)(Ag + j * 4);
    #pragma unroll
    for (int j = 0; j < 4; j++) pb[j] = *(const float4*)(Bg + j * 4);

    const int NST = D / 32;   // 24
    for (int s = 0; s < NST; s++) {
        const int buf = s & 1;
        {
            unsigned ua[4], ub[8];
            #pragma unroll
            for (int j = 0; j < 2; j++) {
                int kb = s * 32 + lkA + j * 4;
                float4 w3v = *(const float4*)(w3 + kb);
                float4 w1v = *(const float4*)(w1 + kb);
                cwacc += pa[j].x * w1v.x + pa[j].y * w1v.y
                       + pa[j].z * w1v.z + pa[j].w * w1v.w;
                ua[2*j]   = pack_bf16(pa[j].x * w3v.x, pa[j].y * w3v.y);
                ua[2*j+1] = pack_bf16(pa[j].z * w3v.z, pa[j].w * w3v.w);
            }
            #pragma unroll
            for (int j = 0; j < 4; j++) {
                int kb = s * 32 + lkB + j * 4;
                float4 w2v = *(const float4*)(w2 + kb);
                qwacc += pb[j].x * w2v.x + pb[j].y * w2v.y
                       + pb[j].z * w2v.z + pb[j].w * w2v.w;
                ub[2*j]   = pack_bf16(pb[j].x, pb[j].y);
                ub[2*j+1] = pack_bf16(pb[j].z, pb[j].w);
            }
            *(uint4*)(As + buf * 64 * 20 + lrA * 20 + lwA) =
                make_uint4(ua[0], ua[1], ua[2], ua[3]);
            unsigned* bp = Bs + buf * 128 * 20 + lrB * 20 + lwB;
            *(uint4*)(bp)     = make_uint4(ub[0], ub[1], ub[2], ub[3]);
            *(uint4*)(bp + 4) = make_uint4(ub[4], ub[5], ub[6], ub[7]);
        }
        __syncthreads();
        if (s + 1 < NST) {
            #pragma unroll
            for (int j = 0; j < 2; j++)
                pa[j] = *(const float4*)(Ag + (s + 1) * 32 + j * 4);
            #pragma unroll
            for (int j = 0; j < 4; j++)
                pb[j] = *(const float4*)(Bg + (s + 1) * 32 + j * 4);
        }
        const unsigned aOff = (unsigned)buf * 64 * 20 * 4;
        const unsigned bOff = (unsigned)buf * 128 * 20 * 4;
        #pragma unroll
        for (int h = 0; h < 2; h++) {
            const unsigned kw = h * 8 * 4;
            unsigned afr[2][4], bfr0[4], bfr1[4];
            ldsm4(afr[0], aSh + aOff + kw + offA[0]);
            ldsm4(afr[1], aSh + aOff + kw + offA[1]);
            ldsm4(bfr0, bSh + bOff + kw + offB[0]);
            ldsm4(bfr1, bSh + bOff + kw + offB[1]);
            #pragma unroll
            for (int mi = 0; mi < 2; mi++)
                #pragma unroll
                for (int ni = 0; ni < 4; ni++) {
                    const unsigned* bp = (ni < 2 ? bfr0 : bfr1) + (ni & 1) * 2;
                    mma_bf16(acc[mi][ni], afr[mi], bp);
                }
        }
    }

    cwacc += __shfl_xor_sync(~0u, cwacc, 1);
    cwacc += __shfl_xor_sync(~0u, cwacc, 2);
    if ((t & 3) == 0) s_cw[lrA] = cwacc;
    qwacc += __shfl_xor_sync(~0u, qwacc, 1);
    if ((t & 1) == 0) s_qw[lrB] = qwacc;
    __syncthreads();

    float qv0[4], qv1[4];
    #pragma unroll
    for (int ni = 0; ni < 4; ni++) {
        int col = wn2 + ni * 8 + 2 * tg;
        qv0[ni] = s_qw[col]; qv1[ni] = s_qw[col + 1];
    }
    const int colb0 = 8 * (tg & 1) + 4 * (tg >> 1);
    #pragma unroll
    for (int mi = 0; mi < 2; mi++) {
        #pragma unroll
        for (int half = 0; half < 2; half++) {
            int rloc = wm2 + mi * 16 + g + half * 8;
            float cw = s_cw[rloc];
            float4 w4[2];
            #pragma unroll
            for (int ni = 0; ni < 4; ni++) {
                float vx = acc[mi][ni][half * 2 + 0] + cw + qv0[ni];
                float vy = acc[mi][ni][half * 2 + 1] + cw + qv1[ni];
                float px = __shfl_xor_sync(~0u, vx, 1);
                float py = __shfl_xor_sync(~0u, vy, 1);
                if ((ni & 1) == (tg & 1)) {
                    int slot = ni >> 1;
                    w4[slot] = (tg & 1) ? make_float4(px, py, vx, vy)
                                        : make_float4(vx, vy, px, py);
                }
            }
            __half* orow = g_sim + ((size_t)b * C + cm + rloc) * Q + wn2;
            float m = -INFINITY;
            #pragma unroll
            for (int it = 0; it < 2; it++) {
                float4 v = w4[it];
                __half2 h0 = __float22half2_rn(make_float2(v.x, v.y));
                __half2 h1 = __float22half2_rn(make_float2(v.z, v.w));
                uint2 hv;
                hv.x = *(unsigned*)&h0;
                hv.y = *(unsigned*)&h1;
                *(uint2*)(orow + colb0 + 16 * it) = hv;
                m = fmaxf(m, fmaxf(fmaxf(v.x, v.y), fmaxf(v.z, v.w)));
            }
            m = fmaxf(m, __shfl_xor_sync(~0u, m, 1));
            m = fmaxf(m, __shfl_xor_sync(~0u, m, 2));
            if (tg == 0) red[(warp >> 1) * 64 + rloc] = m;
        }
    }
    __syncthreads();
    if (t < 64)
        g_Smax[b * C + cm + t] = fmaxf(fmaxf(red[t], red[64 + t]),
                                       fmaxf(red[128 + t], red[192 + t]));

    // ---- fused ques transpose: this block handles 3 of 24 d-tiles for b ----
    {
        float* tile = (float*)smemu;           // 128 x 33 floats (16.9 KB)
        const int q  = t >> 1, cs = (t & 1) * 16;
        const int dd = t >> 3, ws = (t & 7) * 8;
        #pragma unroll 1
        for (int i = 0; i < 3; i++) {
            const int d0 = (blockIdx.x * 3 + i) * 32;
            __syncthreads();                   // smem free / prev tile read done
            const float* src = ques + ((size_t)b * Q + q) * D + d0 + cs;
            #pragma unroll
            for (int j = 0; j < 4; j++) {
                float4 v = *(const float4*)(src + 4 * j);
                tile[q * 33 + cs + 4*j + 0] = v.x;
                tile[q * 33 + cs + 4*j + 1] = v.y;
                tile[q * 33 + cs + 4*j + 2] = v.z;
                tile[q * 33 + cs + 4*j + 3] = v.w;
            }
            __syncthreads();
            unsigned w[8];
            #pragma unroll
            for (int j = 0; j < 8; j++) {
                int wq = ws + j;
                w[j] = pack_bf16(tile[(2 * wq) * 33 + dd],
                                 tile[(2 * wq + 1) * 33 + dd]);
            }
            unsigned* dst = g_quesT + ((size_t)(b * D + d0 + dd)) * 64 + ws;
            *(uint4*)(dst)     = make_uint4(w[0], w[1], w[2], w[3]);
            *(uint4*)(dst + 4) = make_uint4(w[4], w[5], w[6], w[7]);
        }
    }
}

// ---------------- K2: cdist (softmax over S_max + cmask) ---------------------
__global__ void k_cdist(const int* __restrict__ cmask) {
    __shared__ float red[128];
    const int b = blockIdx.x;
    const int t = threadIdx.x;   // 128
    float v[4];
    #pragma unroll
    for (int j = 0; j < 4; j++) {
        int c = j * 128 + t;
        v[j] = g_Smax[b * C + c] + (1.0f - (float)cmask[b * C + c]) * NEG;
    }
    float m = fmaxf(fmaxf(v[0], v[1]), fmaxf(v[2], v[3]));
    red[t] = m;
    __syncthreads();
    for (int s = 64; s; s >>= 1) {
        if (t < s) red[t] = fmaxf(red[t], red[t + s]);
        __syncthreads();
    }
    m = red[0];
    __syncthreads();
    float e[4], ss = 0.f;
    #pragma unroll
    for (int j = 0; j < 4; j++) { e[j] = __expf(v[j] - m); ss += e[j]; }
    red[t] = ss;
    __syncthreads();
    for (int s = 64; s; s >>= 1) {
        if (t < s) red[t] += red[t + s];
        __syncthreads();
    }
    float inv = 1.0f / red[0];
    #pragma unroll
    for (int j = 0; j < 4; j++) g_cdist[b * C + j * 128 + t] = e[j] * inv;
}

// ---------------- K3: fused colpart ∪ cdash_part (NCC=32) --------------------
__global__ void k_pc(const float* __restrict__ cont, const int* __restrict__ qmask) {
    const int b = blockIdx.x, y = blockIdx.y;
    const int t = threadIdx.x;   // 128
    if (y < 96) {
        int dch = y >> 5, cch = y & 31;
        int d = dch * 256 + t * 2;
        __shared__ float sd[C / NCC];   // 16
        if (t < C / NCC)
            sd[t] = g_cdist[b * C + cch * (C / NCC) + t];
        __syncthreads();
        const float* cb = cont + (size_t)(b * C + cch * (C / NCC)) * D + d;
        float ax[8] = {0.f,0.f,0.f,0.f,0.f,0.f,0.f,0.f};
        float ay[8] = {0.f,0.f,0.f,0.f,0.f,0.f,0.f,0.f};
        #pragma unroll
        for (int c0 = 0; c0 < 2; c0++) {
            #pragma unroll
            for (int u = 0; u < 8; u++) {
                int c = u * 2 + c0;
                float2 vv = *(const float2*)&cb[(size_t)c * D];
                float w = sd[c];
                ax[u] = fmaf(w, vv.x, ax[u]);
                ay[u] = fmaf(w, vv.y, ay[u]);
            }
        }
        float sx = ((ax[0]+ax[1])+(ax[2]+ax[3])) + ((ax[4]+ax[5])+(ax[6]+ax[7]));
        float sy = ((ay[0]+ay[1])+(ay[2]+ay[3])) + ((ay[4]+ay[5])+(ay[6]+ay[7]));
        *(float2*)&g_cdashp[cch][b * D + d] = make_float2(sx, sy);
    } else {
        int ch = y - 96;
        float addend = (1.0f - (float)qmask[b * Q + t]) * NEG;
        const __half* base = g_sim + ((size_t)b * C + ch * (C / NCH)) * Q + t;
        float v[C / NCH];
        float m = -INFINITY;
        #pragma unroll
        for (int c = 0; c < C / NCH; c++) {
            v[c] = __half2float(base[(size_t)c * Q]) + addend;
            m = fmaxf(m, v[c]);
        }
        float s = 0.f;
        #pragma unroll
        for (int c = 0; c < C / NCH; c++) s += __expf(v[c] - m);
        g_pmax[(b * NCH + ch) * Q + t] = m;
        g_psum[(b * NCH + ch) * Q + t] = s;
    }
}

// ---------------- K4: c2q, M-tile 128, 512 threads = 2 dn warp-groups --------
__global__ __launch_bounds__(512) void k_c2q_mma(const float* __restrict__ cont,
                                                 const int*   __restrict__ qmask,
                                                 float* __restrict__ out) {
    const int b  = blockIdx.z;
    const int cm = blockIdx.x * 128;
    extern __shared__ unsigned smemu[];
    unsigned* P  = smemu;                      // 128*68
    unsigned* Bs = smemu + 128 * 68;           // [2 wg][2 buf][128][68]
    float* s_add   = (float*)(Bs + 4 * 128 * 68);
    float* s_max   = s_add + 128;
    float* s_inv   = s_max + 128;
    float* s_cdash = s_inv + 128;              // 768

    const int t  = threadIdx.x;
    const int wg = t >> 8;                     // warp-group 0/1
    const int wt = t & 255;
    const int lane = wt & 31, warp = wt >> 5;
    const int g = lane >> 2, tg = lane & 3;
    const int wm = (warp & 3) * 32;
    const int wn = (warp >> 2) * 64;

    unsigned* gBs = Bs + wg * 2 * 128 * 68;    // this group's double buffer

    const int rA = (lane & 7) + (lane & 8);
    const int cA = (lane & 16) >> 2;
    const int rB = (lane & 7) + ((lane & 16) >> 1);
    const int cB = (lane & 8) >> 1;
    const unsigned pSh = (unsigned)__cvta_generic_to_shared(P);
    const unsigned bSh = (unsigned)__cvta_generic_to_shared(gBs);
    unsigned offA0 = ((wm + rA) * 68 + cA) * 4;
    unsigned offA1 = offA0 + 16 * 68 * 4;
    unsigned offB[4];
    #pragma unroll
    for (int p = 0; p < 4; p++) offB[p] = ((wn + p * 16 + rB) * 68 + cB) * 4;

    // prologue: colfin merge + cdash reduce
    if (t < Q) {
        s_add[t] = (1.0f - (float)qmask[b * Q + t]) * NEG;
        float pm[NCH];
        float m = -INFINITY;
        #pragma unroll
        for (int ch = 0; ch < NCH; ch++) {
            pm[ch] = g_pmax[(b * NCH + ch) * Q + t];
            m = fmaxf(m, pm[ch]);
        }
        float s = 0.f;
        #pragma unroll
        for (int ch = 0; ch < NCH; ch++)
            s += g_psum[(b * NCH + ch) * Q + t] * __expf(pm[ch] - m);
        s_max[t] = m;
        s_inv[t] = 1.0f / s;
    }
    for (int d = t; d < D; d += 512) {
        float s = 0.f;
        #pragma unroll
        for (int u = 0; u < NCC; u++) s += g_cdashp[u][b * D + d];
        s_cdash[d] = s;
    }
    // P build needs s_add/max/inv: barrier 0 first
    __syncthreads();

    {   // build P: 512 threads, 128 rows, 32 q per thread
        const int lr = t >> 2;
        const int lk = (t & 3) * 32;
        const __half* simrow = g_sim + ((size_t)(b * C + cm + lr)) * Q + lk;
        #pragma unroll
        for (int j = 0; j < 8; j++) {
            int q0 = lk + j * 4;
            uint2 hv = *(const uint2*)(simrow + j * 4);
            __half2 h0 = *(__half2*)&hv.x;
            __half2 h1 = *(__half2*)&hv.y;
            float2 f0 = __half22float2(h0);
            float2 f1 = __half22float2(h1);
            float e0 = __expf((f0.x + s_add[q0+0]) - s_max[q0+0]) * s_inv[q0+0];
            float e1 = __expf((f0.y + s_add[q0+1]) - s_max[q0+1]) * s_inv[q0+1];
            float e2 = __expf((f1.x + s_add[q0+2]) - s_max[q0+2]) * s_inv[q0+2];
            float e3 = __expf((f1.y + s_add[q0+3]) - s_max[q0+3]) * s_inv[q0+3];
            *(uint2*)(P + lr * 68 + (q0 >> 1)) =
                make_uint2(pack_bf16(e0, e1), pack_bf16(e2, e3));
        }
    }

    const int fr = wt >> 1;
    const int fw = (wt & 1) * 32;
    const unsigned* qT = g_quesT + (size_t)b * D * 64;

    {   // issue this group's first tile (dn = wg*3) into buf 0
        const unsigned* src = qT + (size_t)(wg * 3 * 128 + fr) * 64 + fw;
        unsigned* dst = gBs + fr * 68 + fw;
        #pragma unroll
        for (int j = 0; j < 8; j++) cp16(dst + 4 * j, src + 4 * j);
        cp_commit();
    }

    __syncthreads();   // P visible to both groups; first fills in flight

    const int colb0 = 8 * (tg & 1) + 4 * (tg >> 1);

    #pragma unroll 1
    for (int i = 0; i < 3; i++) {
        const int dn  = wg * 3 + i;
        const int buf = i & 1;
        cp_wait0();
        asm volatile("bar.sync %0, %1;" :: "r"(1 + wg), "r"(256) : "memory");
        if (i + 1 < 3) {
            const unsigned* src = qT + (size_t)((dn + 1) * 128 + fr) * 64 + fw;
            unsigned* dst = gBs + (buf ^ 1) * 128 * 68 + fr * 68 + fw;
            #pragma unroll
            for (int j = 0; j < 8; j++) cp16(dst + 4 * j, src + 4 * j);
            cp_commit();
        }

        float acc[2][8][4];
        #pragma unroll
        for (int ii = 0; ii < 2; ii++)
            #pragma unroll
            for (int j = 0; j < 8; j++)
                #pragma unroll
                for (int k = 0; k < 4; k++) acc[ii][j][k] = 0.f;

        const unsigned bufOff = (unsigned)buf * 128 * 68 * 4;
        #pragma unroll
        for (int kk = 0; kk < 8; kk++) {
            const unsigned kw = kk * 8 * 4;
            unsigned afr[2][4];
            ldsm4(afr[0], pSh + kw + offA0);
            ldsm4(afr[1], pSh + kw + offA1);
            #pragma unroll
            for (int p = 0; p < 4; p++) {
                unsigned bfr[4];
                ldsm4(bfr, bSh + bufOff + kw + offB[p]);
                mma_bf16(acc[0][2*p],   afr[0], bfr);
                mma_bf16(acc[1][2*p],   afr[1], bfr);
                mma_bf16(acc[0][2*p+1], afr[0], bfr + 2);
                mma_bf16(acc[1][2*p+1], afr[1], bfr + 2);
            }
        }

        #pragma unroll
        for (int mi = 0; mi < 2; mi++) {
            #pragma unroll
            for (int half = 0; half < 2; half++) {
                float4 w4[4];
                #pragma unroll
                for (int ni = 0; ni < 8; ni++) {
                    float vx = acc[mi][ni][half * 2 + 0];
                    float vy = acc[mi][ni][half * 2 + 1];
                    float px = __shfl_xor_sync(~0u, vx, 1);
                    float py = __shfl_xor_sync(~0u, vy, 1);
                    if ((ni & 1) == (tg & 1)) {
                        int slot = ni >> 1;
                        w4[slot] = (tg & 1) ? make_float4(px, py, vx, vy)
                                            : make_float4(vx, vy, px, py);
                    }
                }
                int cc = cm + wm + mi * 16 + g + half * 8;
                const float* crow = cont + ((size_t)b * C + cc) * D + dn * 128;
                float* obase = out + ((size_t)b * C + cc) * (4 * D);
                #pragma unroll
                for (int it = 0; it < 4; it++) {
                    int col = wn + colb0 + 16 * it;
                    int dg  = dn * 128 + col;
                    float4 cv = *(const float4*)(crow + col);
                    float4 cd = *(const float4*)&s_cdash[dg];
                    float4 v  = w4[it];
                    *(float4*)&obase[dg]         = cv;
                    *(float4*)&obase[D + dg]     = v;
                    *(float4*)&obase[2 * D + dg] = make_float4(cv.x * v.x,  cv.y * v.y,
                                                               cv.z * v.z,  cv.w * v.w);
                    *(float4*)&obase[3 * D + dg] = make_float4(cv.x * cd.x, cv.y * cd.y,
                                                               cv.z * cd.z, cv.w * cd.w);
                }
            }
        }
    }
}

// ---------------- launch -----------------------------------------------------
extern "C" void kernel_launch(void* const* d_in, const int* in_sizes, int n_in,
                              void* d_out, int out_size) {
    const float* cont  = (const float*)d_in[0];
    const int*   cmask = (const int*)d_in[1];
    const float* ques  = (const float*)d_in[2];
    const int*   qmask = (const int*)d_in[3];
    const float* SW    = (const float*)d_in[4];
    float* out = (float*)d_out;

    const int smem_sim = (2 * 64 * 20 + 2 * 128 * 20) * 4 + (256 + 64 + 128) * 4;
    const int smem_c2q = (128 * 68 + 4 * 128 * 68) * 4 + (3 * 128 + 768) * 4;  // 178688
    cudaFuncSetAttribute(k_sim_mma, cudaFuncAttributeMaxDynamicSharedMemorySize, smem_sim);
    cudaFuncSetAttribute(k_c2q_mma, cudaFuncAttributeMaxDynamicSharedMemorySize, smem_c2q);

    k_sim_mma<<<dim3(C / 64, 1, B), 256, smem_sim>>>(cont, ques, SW);
    k_cdist<<<B, 128>>>(cmask);
    k_pc<<<dim3(B, 112), 128>>>(cont, qmask);
    k_c2q_mma<<<dim3(C / 128, 1, B), 512, smem_c2q>>>(cont, qmask, out);
}

// round 16
// speedup vs baseline: 1.0323x; 1.0323x over previous
#include <cuda_runtime.h>
#include <cuda_fp16.h>
#include <math.h>

#define B 32
#define C 512
#define Q 128
#define D 768
#define NEG (-1e30f)
#define NCH 16
#define NCC 32

// ---------------- scratch ----------------------------------------------------
__device__ __half g_sim[(size_t)B * C * Q];      // fp16 sim (4.2 MB)
__device__ float g_Smax[B * C];
__device__ float g_pmax[B * NCH * Q];
__device__ float g_psum[B * NCH * Q];
__device__ float g_cdist[B * C];
__device__ float g_cdashp[NCC][B * D];
__device__ __align__(16) unsigned g_quesT[(size_t)B * D * (Q / 2)];

// ---------------- helpers ----------------------------------------------------
__device__ __forceinline__ unsigned pack_bf16(float lo, float hi) {
    unsigned r; asm("cvt.rn.bf16x2.f32 %0, %1, %2;" : "=r"(r) : "f"(hi), "f"(lo));
    return r;
}
__device__ __forceinline__ void mma_bf16(float* d, const unsigned* a, const unsigned* b) {
    asm volatile("mma.sync.aligned.m16n8k16.row.col.f32.bf16.bf16.f32 "
                 "{%0,%1,%2,%3}, {%4,%5,%6,%7}, {%8,%9}, {%0,%1,%2,%3};"
                 : "+f"(d[0]), "+f"(d[1]), "+f"(d[2]), "+f"(d[3])
                 : "r"(a[0]), "r"(a[1]), "r"(a[2]), "r"(a[3]), "r"(b[0]), "r"(b[1]));
}
__device__ __forceinline__ void ldsm4(unsigned* r, unsigned addr) {
    asm volatile("ldmatrix.sync.aligned.m8n8.x4.shared.b16 {%0,%1,%2,%3}, [%4];"
                 : "=r"(r[0]), "=r"(r[1]), "=r"(r[2]), "=r"(r[3]) : "r"(addr));
}
__device__ __forceinline__ void cp16(void* smem_dst, const void* gsrc) {
    unsigned ds = (unsigned)__cvta_generic_to_shared(smem_dst);
    asm volatile("cp.async.cg.shared.global [%0], [%1], 16;" :: "r"(ds), "l"(gsrc));
}
__device__ __forceinline__ void cp_commit() { asm volatile("cp.async.commit_group;"); }
__device__ __forceinline__ void cp_wait0()  { asm volatile("cp.async.wait_group 0;"); }

// ---------------- K1: sim GEMM (M-tile 64, 2 CTAs/SM) + fused ques transpose -
__global__ __launch_bounds__(256, 2) void k_sim_mma(const float* __restrict__ cont,
                                                    const float* __restrict__ ques,
                                                    const float* __restrict__ SW) {
    const int b  = blockIdx.z;
    const int cm = blockIdx.x * 64;
    extern __shared__ unsigned smemu[];
    unsigned* As = smemu;                      // [2][64][20]
    unsigned* Bs = smemu + 2 * 64 * 20;        // [2][128][20]
    float*   red = (float*)(Bs + 2 * 128 * 20); // 256
    float*  s_cw = red + 256;                  // 64
    float*  s_qw = s_cw + 64;                  // 128

    const int t = threadIdx.x, lane = t & 31, warp = t >> 5;
    const int g = lane >> 2, tg = lane & 3;
    const int wm2 = (warp & 1) * 32;
    const int wn2 = (warp >> 1) * 32;

    const int rA = (lane & 7) + (lane & 8);
    const int cA = (lane & 16) >> 2;
    const int rB = (lane & 7) + ((lane & 16) >> 1);
    const int cB = (lane & 8) >> 1;
    const unsigned aSh = (unsigned)__cvta_generic_to_shared(As);
    const unsigned bSh = (unsigned)__cvta_generic_to_shared(Bs);
    unsigned offA[2];
    offA[0] = ((wm2 + rA) * 20 + cA) * 4;
    offA[1] = offA[0] + 16 * 20 * 4;
    unsigned offB[2];
    #pragma unroll
    for (int p = 0; p < 2; p++) offB[p] = ((wn2 + p * 16 + rB) * 20 + cB) * 4;

    const float* w1 = SW;
    const float* w2 = SW + D;
    const float* w3 = SW + 2 * D;
    const int lrA = t >> 2, lkA = (t & 3) * 8, lwA = (t & 3) * 4;
    const int lrB = t >> 1, lkB = (t & 1) * 16, lwB = (t & 1) * 8;
    const float* Ag = cont + ((size_t)(b * C + cm + lrA)) * D + lkA;
    const float* Bg = ques + ((size_t)(b * Q + lrB)) * D + lkB;

    float acc[2][4][4];
    #pragma unroll
    for (int i = 0; i < 2; i++)
        #pragma unroll
        for (int j = 0; j < 4; j++)
            #pragma unroll
            for (int k = 0; k < 4; k++) acc[i][j][k] = 0.f;

    float cwacc = 0.f, qwacc = 0.f;

    float4 pa[2], pb[4];
    #pragma unroll
    for (int j = 0; j < 2; j++) pa[j] = *(const float4*)(Ag + j * 4);
    #pragma unroll
    for (int j = 0; j < 4; j++) pb[j] = *(const float4*)(Bg + j * 4);

    const int NST = D / 32;   // 24
    for (int s = 0; s < NST; s++) {
        const int buf = s & 1;
        {
            unsigned ua[4], ub[8];
            #pragma unroll
            for (int j = 0; j < 2; j++) {
                int kb = s * 32 + lkA + j * 4;
                float4 w3v = *(const float4*)(w3 + kb);
                float4 w1v = *(const float4*)(w1 + kb);
                cwacc += pa[j].x * w1v.x + pa[j].y * w1v.y
                       + pa[j].z * w1v.z + pa[j].w * w1v.w;
                ua[2*j]   = pack_bf16(pa[j].x * w3v.x, pa[j].y * w3v.y);
                ua[2*j+1] = pack_bf16(pa[j].z * w3v.z, pa[j].w * w3v.w);
            }
            #pragma unroll
            for (int j = 0; j < 4; j++) {
                int kb = s * 32 + lkB + j * 4;
                float4 w2v = *(const float4*)(w2 + kb);
                qwacc += pb[j].x * w2v.x + pb[j].y * w2v.y
                       + pb[j].z * w2v.z + pb[j].w * w2v.w;
                ub[2*j]   = pack_bf16(pb[j].x, pb[j].y);
                ub[2*j+1] = pack_bf16(pb[j].z, pb[j].w);
            }
            *(uint4*)(As + buf * 64 * 20 + lrA * 20 + lwA) =
                make_uint4(ua[0], ua[1], ua[2], ua[3]);
            unsigned* bp = Bs + buf * 128 * 20 + lrB * 20 + lwB;
            *(uint4*)(bp)     = make_uint4(ub[0], ub[1], ub[2], ub[3]);
            *(uint4*)(bp + 4) = make_uint4(ub[4], ub[5], ub[6], ub[7]);
        }
        __syncthreads();
        if (s + 1 < NST) {
            #pragma unroll
            for (int j = 0; j < 2; j++)
                pa[j] = *(const float4*)(Ag + (s + 1) * 32 + j * 4);
            #pragma unroll
            for (int j = 0; j < 4; j++)
                pb[j] = *(const float4*)(Bg + (s + 1) * 32 + j * 4);
        }
        const unsigned aOff = (unsigned)buf * 64 * 20 * 4;
        const unsigned bOff = (unsigned)buf * 128 * 20 * 4;
        #pragma unroll
        for (int h = 0; h < 2; h++) {
            const unsigned kw = h * 8 * 4;
            unsigned afr[2][4], bfr0[4], bfr1[4];
            ldsm4(afr[0], aSh + aOff + kw + offA[0]);
            ldsm4(afr[1], aSh + aOff + kw + offA[1]);
            ldsm4(bfr0, bSh + bOff + kw + offB[0]);
            ldsm4(bfr1, bSh + bOff + kw + offB[1]);
            #pragma unroll
            for (int mi = 0; mi < 2; mi++)
                #pragma unroll
                for (int ni = 0; ni < 4; ni++) {
                    const unsigned* bp = (ni < 2 ? bfr0 : bfr1) + (ni & 1) * 2;
                    mma_bf16(acc[mi][ni], afr[mi], bp);
                }
        }
    }

    cwacc += __shfl_xor_sync(~0u, cwacc, 1);
    cwacc += __shfl_xor_sync(~0u, cwacc, 2);
    if ((t & 3) == 0) s_cw[lrA] = cwacc;
    qwacc += __shfl_xor_sync(~0u, qwacc, 1);
    if ((t & 1) == 0) s_qw[lrB] = qwacc;
    __syncthreads();

    float qv0[4], qv1[4];
    #pragma unroll
    for (int ni = 0; ni < 4; ni++) {
        int col = wn2 + ni * 8 + 2 * tg;
        qv0[ni] = s_qw[col]; qv1[ni] = s_qw[col + 1];
    }
    const int colb0 = 8 * (tg & 1) + 4 * (tg >> 1);
    #pragma unroll
    for (int mi = 0; mi < 2; mi++) {
        #pragma unroll
        for (int half = 0; half < 2; half++) {
            int rloc = wm2 + mi * 16 + g + half * 8;
            float cw = s_cw[rloc];
            float4 w4[2];
            #pragma unroll
            for (int ni = 0; ni < 4; ni++) {
                float vx = acc[mi][ni][half * 2 + 0] + cw + qv0[ni];
                float vy = acc[mi][ni][half * 2 + 1] + cw + qv1[ni];
                float px = __shfl_xor_sync(~0u, vx, 1);
                float py = __shfl_xor_sync(~0u, vy, 1);
                if ((ni & 1) == (tg & 1)) {
                    int slot = ni >> 1;
                    w4[slot] = (tg & 1) ? make_float4(px, py, vx, vy)
                                        : make_float4(vx, vy, px, py);
                }
            }
            __half* orow = g_sim + ((size_t)b * C + cm + rloc) * Q + wn2;
            float m = -INFINITY;
            #pragma unroll
            for (int it = 0; it < 2; it++) {
                float4 v = w4[it];
                __half2 h0 = __float22half2_rn(make_float2(v.x, v.y));
                __half2 h1 = __float22half2_rn(make_float2(v.z, v.w));
                uint2 hv;
                hv.x = *(unsigned*)&h0;
                hv.y = *(unsigned*)&h1;
                *(uint2*)(orow + colb0 + 16 * it) = hv;
                m = fmaxf(m, fmaxf(fmaxf(v.x, v.y), fmaxf(v.z, v.w)));
            }
            m = fmaxf(m, __shfl_xor_sync(~0u, m, 1));
            m = fmaxf(m, __shfl_xor_sync(~0u, m, 2));
            if (tg == 0) red[(warp >> 1) * 64 + rloc] = m;
        }
    }
    __syncthreads();
    if (t < 64)
        g_Smax[b * C + cm + t] = fmaxf(fmaxf(red[t], red[64 + t]),
                                       fmaxf(red[128 + t], red[192 + t]));

    // ---- fused ques transpose: this block handles 3 of 24 d-tiles for b ----
    {
        float* tile = (float*)smemu;           // 128 x 33 floats
        const int q  = t >> 1, cs = (t & 1) * 16;
        const int dd = t >> 3, ws = (t & 7) * 8;
        #pragma unroll 1
        for (int i = 0; i < 3; i++) {
            const int d0 = (blockIdx.x * 3 + i) * 32;
            __syncthreads();
            const float* src = ques + ((size_t)b * Q + q) * D + d0 + cs;
            #pragma unroll
            for (int j = 0; j < 4; j++) {
                float4 v = *(const float4*)(src + 4 * j);
                tile[q * 33 + cs + 4*j + 0] = v.x;
                tile[q * 33 + cs + 4*j + 1] = v.y;
                tile[q * 33 + cs + 4*j + 2] = v.z;
                tile[q * 33 + cs + 4*j + 3] = v.w;
            }
            __syncthreads();
            unsigned w[8];
            #pragma unroll
            for (int j = 0; j < 8; j++) {
                int wq = ws + j;
                w[j] = pack_bf16(tile[(2 * wq) * 33 + dd],
                                 tile[(2 * wq + 1) * 33 + dd]);
            }
            unsigned* dst = g_quesT + ((size_t)(b * D + d0 + dd)) * 64 + ws;
            *(uint4*)(dst)     = make_uint4(w[0], w[1], w[2], w[3]);
            *(uint4*)(dst + 4) = make_uint4(w[4], w[5], w[6], w[7]);
        }
    }
}

// ---------------- K2: cdist (softmax over S_max + cmask) ---------------------
__global__ void k_cdist(const int* __restrict__ cmask) {
    __shared__ float red[128];
    const int b = blockIdx.x;
    const int t = threadIdx.x;   // 128
    float v[4];
    #pragma unroll
    for (int j = 0; j < 4; j++) {
        int c = j * 128 + t;
        v[j] = g_Smax[b * C + c] + (1.0f - (float)cmask[b * C + c]) * NEG;
    }
    float m = fmaxf(fmaxf(v[0], v[1]), fmaxf(v[2], v[3]));
    red[t] = m;
    __syncthreads();
    for (int s = 64; s; s >>= 1) {
        if (t < s) red[t] = fmaxf(red[t], red[t + s]);
        __syncthreads();
    }
    m = red[0];
    __syncthreads();
    float e[4], ss = 0.f;
    #pragma unroll
    for (int j = 0; j < 4; j++) { e[j] = __expf(v[j] - m); ss += e[j]; }
    red[t] = ss;
    __syncthreads();
    for (int s = 64; s; s >>= 1) {
        if (t < s) red[t] += red[t + s];
        __syncthreads();
    }
    float inv = 1.0f / red[0];
    #pragma unroll
    for (int j = 0; j < 4; j++) g_cdist[b * C + j * 128 + t] = e[j] * inv;
}

// ---------------- K3: fused colpart ∪ cdash_part (NCC=32) --------------------
__global__ void k_pc(const float* __restrict__ cont, const int* __restrict__ qmask) {
    const int b = blockIdx.x, y = blockIdx.y;
    const int t = threadIdx.x;   // 128
    if (y < 96) {
        int dch = y >> 5, cch = y & 31;
        int d = dch * 256 + t * 2;
        __shared__ float sd[C / NCC];   // 16
        if (t < C / NCC)
            sd[t] = g_cdist[b * C + cch * (C / NCC) + t];
        __syncthreads();
        const float* cb = cont + (size_t)(b * C + cch * (C / NCC)) * D + d;
        float ax[8] = {0.f,0.f,0.f,0.f,0.f,0.f,0.f,0.f};
        float ay[8] = {0.f,0.f,0.f,0.f,0.f,0.f,0.f,0.f};
        #pragma unroll
        for (int c0 = 0; c0 < 2; c0++) {
            #pragma unroll
            for (int u = 0; u < 8; u++) {
                int c = u * 2 + c0;
                float2 vv = *(const float2*)&cb[(size_t)c * D];
                float w = sd[c];
                ax[u] = fmaf(w, vv.x, ax[u]);
                ay[u] = fmaf(w, vv.y, ay[u]);
            }
        }
        float sx = ((ax[0]+ax[1])+(ax[2]+ax[3])) + ((ax[4]+ax[5])+(ax[6]+ax[7]));
        float sy = ((ay[0]+ay[1])+(ay[2]+ay[3])) + ((ay[4]+ay[5])+(ay[6]+ay[7]));
        *(float2*)&g_cdashp[cch][b * D + d] = make_float2(sx, sy);
    } else {
        int ch = y - 96;
        float addend = (1.0f - (float)qmask[b * Q + t]) * NEG;
        const __half* base = g_sim + ((size_t)b * C + ch * (C / NCH)) * Q + t;
        float v[C / NCH];
        float m = -INFINITY;
        #pragma unroll
        for (int c = 0; c < C / NCH; c++) {
            v[c] = __half2float(base[(size_t)c * Q]) + addend;
            m = fmaxf(m, v[c]);
        }
        float s = 0.f;
        #pragma unroll
        for (int c = 0; c < C / NCH; c++) s += __expf(v[c] - m);
        g_pmax[(b * NCH + ch) * Q + t] = m;
        g_psum[(b * NCH + ch) * Q + t] = s;
    }
}

// ---------------- K4: c2q = P @ quesT, M-tile 128, .cs output stores ---------
__global__ __launch_bounds__(256) void k_c2q_mma(const float* __restrict__ cont,
                                                 const int*   __restrict__ qmask,
                                                 float* __restrict__ out) {
    const int b  = blockIdx.z;
    const int cm = blockIdx.x * 128;
    extern __shared__ unsigned smemu[];
    unsigned* P  = smemu;                      // 128*68
    unsigned* Bs = smemu + 128 * 68;           // 2*128*68
    float* s_add   = (float*)(Bs + 2 * 128 * 68);
    float* s_max   = s_add + 128;
    float* s_inv   = s_max + 128;
    float* s_cdash = s_inv + 128;              // 768

    const int t = threadIdx.x, lane = t & 31, warp = t >> 5;
    const int g = lane >> 2, tg = lane & 3;
    const int wm = (warp & 3) * 32;
    const int wn = (warp >> 2) * 64;

    const int rA = (lane & 7) + (lane & 8);
    const int cA = (lane & 16) >> 2;
    const int rB = (lane & 7) + ((lane & 16) >> 1);
    const int cB = (lane & 8) >> 1;
    const unsigned pSh = (unsigned)__cvta_generic_to_shared(P);
    const unsigned bSh = (unsigned)__cvta_generic_to_shared(Bs);
    unsigned offA0 = ((wm + rA) * 68 + cA) * 4;
    unsigned offA1 = offA0 + 16 * 68 * 4;
    unsigned offB[4];
    #pragma unroll
    for (int p = 0; p < 4; p++) offB[p] = ((wn + p * 16 + rB) * 68 + cB) * 4;

    if (t < Q) {
        s_add[t] = (1.0f - (float)qmask[b * Q + t]) * NEG;
        float pm[NCH];
        float m = -INFINITY;
        #pragma unroll
        for (int ch = 0; ch < NCH; ch++) {
            pm[ch] = g_pmax[(b * NCH + ch) * Q + t];
            m = fmaxf(m, pm[ch]);
        }
        float s = 0.f;
        #pragma unroll
        for (int ch = 0; ch < NCH; ch++)
            s += g_psum[(b * NCH + ch) * Q + t] * __expf(pm[ch] - m);
        s_max[t] = m;
        s_inv[t] = 1.0f / s;
    }
    for (int d = t; d < D; d += 256) {
        float s = 0.f;
        #pragma unroll
        for (int u = 0; u < NCC; u++) s += g_cdashp[u][b * D + d];
        s_cdash[d] = s;
    }
    __syncthreads();

    const int lr = t >> 1;
    const int lk = (t & 1) * 16;
    {
        const __half* simrow = g_sim + ((size_t)(b * C + cm + lr)) * Q + lk;
        #pragma unroll
        for (int sc = 0; sc < 4; sc++) {
            #pragma unroll
            for (int j = 0; j < 4; j++) {
                int q0 = sc * 32 + lk + j * 4;
                uint2 hv = *(const uint2*)(simrow + sc * 32 + j * 4);
                __half2 h0 = *(__half2*)&hv.x;
                __half2 h1 = *(__half2*)&hv.y;
                float2 f0 = __half22float2(h0);
                float2 f1 = __half22float2(h1);
                float e0 = __expf((f0.x + s_add[q0+0]) - s_max[q0+0]) * s_inv[q0+0];
                float e1 = __expf((f0.y + s_add[q0+1]) - s_max[q0+1]) * s_inv[q0+1];
                float e2 = __expf((f1.x + s_add[q0+2]) - s_max[q0+2]) * s_inv[q0+2];
                float e3 = __expf((f1.y + s_add[q0+3]) - s_max[q0+3]) * s_inv[q0+3];
                *(uint2*)(P + lr * 68 + (q0 >> 1)) =
                    make_uint2(pack_bf16(e0, e1), pack_bf16(e2, e3));
            }
        }
    }

    const int fr = t >> 1;
    const int fw = (t & 1) * 32;
    const unsigned* qT = g_quesT + (size_t)b * D * 64;

    {
        const unsigned* src = qT + (size_t)fr * 64 + fw;
        unsigned* dst = Bs + fr * 68 + fw;
        #pragma unroll
        for (int j = 0; j < 8; j++) cp16(dst + 4 * j, src + 4 * j);
        cp_commit();
    }

    const int colb0 = 8 * (tg & 1) + 4 * (tg >> 1);

    for (int dn = 0; dn < 6; dn++) {
        const int buf = dn & 1;
        cp_wait0();
        __syncthreads();
        if (dn + 1 < 6) {
            const unsigned* src = qT + (size_t)((dn + 1) * 128 + fr) * 64 + fw;
            unsigned* dst = Bs + (buf ^ 1) * 128 * 68 + fr * 68 + fw;
            #pragma unroll
            for (int j = 0; j < 8; j++) cp16(dst + 4 * j, src + 4 * j);
            cp_commit();
        }

        float acc[2][8][4];
        #pragma unroll
        for (int i = 0; i < 2; i++)
            #pragma unroll
            for (int j = 0; j < 8; j++)
                #pragma unroll
                for (int k = 0; k < 4; k++) acc[i][j][k] = 0.f;

        const unsigned bufOff = (unsigned)buf * 128 * 68 * 4;
        #pragma unroll
        for (int kk = 0; kk < 8; kk++) {
            const unsigned kw = kk * 8 * 4;
            unsigned afr[2][4];
            ldsm4(afr[0], pSh + kw + offA0);
            ldsm4(afr[1], pSh + kw + offA1);
            #pragma unroll
            for (int p = 0; p < 4; p++) {
                unsigned bfr[4];
                ldsm4(bfr, bSh + bufOff + kw + offB[p]);
                mma_bf16(acc[0][2*p],   afr[0], bfr);
                mma_bf16(acc[1][2*p],   afr[1], bfr);
                mma_bf16(acc[0][2*p+1], afr[0], bfr + 2);
                mma_bf16(acc[1][2*p+1], afr[1], bfr + 2);
            }
        }

        #pragma unroll
        for (int mi = 0; mi < 2; mi++) {
            #pragma unroll
            for (int half = 0; half < 2; half++) {
                float4 w4[4];
                #pragma unroll
                for (int ni = 0; ni < 8; ni++) {
                    float vx = acc[mi][ni][half * 2 + 0];
                    float vy = acc[mi][ni][half * 2 + 1];
                    float px = __shfl_xor_sync(~0u, vx, 1);
                    float py = __shfl_xor_sync(~0u, vy, 1);
                    if ((ni & 1) == (tg & 1)) {
                        int slot = ni >> 1;
                        w4[slot] = (tg & 1) ? make_float4(px, py, vx, vy)
                                            : make_float4(vx, vy, px, py);
                    }
                }
                int cc = cm + wm + mi * 16 + g + half * 8;
                const float* crow = cont + ((size_t)b * C + cc) * D + dn * 128;
                float* obase = out + ((size_t)b * C + cc) * (4 * D);
                #pragma unroll
                for (int it = 0; it < 4; it++) {
                    int col = wn + colb0 + 16 * it;
                    int dg  = dn * 128 + col;
                    float4 cv = *(const float4*)(crow + col);
                    float4 cd = *(const float4*)&s_cdash[dg];
                    float4 v  = w4[it];
                    __stcs((float4*)&obase[dg], cv);
                    __stcs((float4*)&obase[D + dg], v);
                    __stcs((float4*)&obase[2 * D + dg],
                           make_float4(cv.x * v.x,  cv.y * v.y,
                                       cv.z * v.z,  cv.w * v.w));
                    __stcs((float4*)&obase[3 * D + dg],
                           make_float4(cv.x * cd.x, cv.y * cd.y,
                                       cv.z * cd.z, cv.w * cd.w));
                }
            }
        }
    }
}

// ---------------- launch -----------------------------------------------------
extern "C" void kernel_launch(void* const* d_in, const int* in_sizes, int n_in,
                              void* d_out, int out_size) {
    const float* cont  = (const float*)d_in[0];
    const int*   cmask = (const int*)d_in[1];
    const float* ques  = (const float*)d_in[2];
    const int*   qmask = (const int*)d_in[3];
    const float* SW    = (const float*)d_in[4];
    float* out = (float*)d_out;

    const int smem_sim = (2 * 64 * 20 + 2 * 128 * 20) * 4 + (256 + 64 + 128) * 4;
    const int smem_c2q = (128 * 68 + 2 * 128 * 68) * 4 + (3 * 128 + 768) * 4;
    cudaFuncSetAttribute(k_sim_mma, cudaFuncAttributeMaxDynamicSharedMemorySize, smem_sim);
    cudaFuncSetAttribute(k_c2q_mma, cudaFuncAttributeMaxDynamicSharedMemorySize, smem_c2q);

    k_sim_mma<<<dim3(C / 64, 1, B), 256, smem_sim>>>(cont, ques, SW);
    k_cdist<<<B, 128>>>(cmask);
    k_pc<<<dim3(B, 112), 128>>>(cont, qmask);
    k_c2q_mma<<<dim3(C / 128, 1, B), 256, smem_c2q>>>(cont, qmask, out);
}